// round 16
// baseline (speedup 1.0000x reference)
#include <cuda_runtime.h>
#include <cuda_bf16.h>
#include <math.h>
#include <cstdint>

#define L      40
#define BATCH  128
#define HIDI   512
#define H      512
#define G4     2048
#define NCLS   7000
#define NPAD   7040
#define HW     256
#define M5     (L*BATCH)   /* 5120 */
#define KCAT   1024

// ---------------- scratch (static device globals: no allocation) ----------------
__device__ float g_xg [M5*G4];
__device__ float g_hem[M5*H];
__device__ float g_fatt[M5*HW];
__device__ float g_c  [BATCH*H];
__device__ float g_part[8*BATCH*G4];
__device__ float g_logits[(size_t)M5*NCLS];
__device__ __nv_bfloat16 g_xtsbf[M5*HIDI];
__device__ __nv_bfloat16 g_catbf[(size_t)M5*KCAT];   // h | att, bf16
__device__ __nv_bfloat16 g_linbf[(size_t)NPAD*KCAT];
__device__ __nv_bfloat16 g_whhbf[G4*H];
__device__ __nv_bfloat16 g_wihbf[G4*HIDI];
__device__ __nv_bfloat16 g_hemwbf[H*H];
__device__ unsigned int g_bar_cnt;
__device__ unsigned int g_bar_gen;

__device__ __forceinline__ float tanh_approx(float x) {
    float y; asm("tanh.approx.f32 %0, %1;" : "=f"(y) : "f"(x)); return y;
}
__device__ __forceinline__ float sigmoid_acc(float x) { return 1.0f / (1.0f + expf(-x)); }

__device__ __forceinline__ uint32_t smem_u32(const void* p) {
    uint32_t a;
    asm("{ .reg .u64 t; cvta.to.shared.u64 t, %1; cvt.u32.u64 %0, t; }" : "=r"(a) : "l"(p));
    return a;
}
__device__ __forceinline__ void ldsm_x4(uint32_t* r, uint32_t addr) {
    asm volatile("ldmatrix.sync.aligned.m8n8.x4.shared.b16 {%0,%1,%2,%3}, [%4];"
                 : "=r"(r[0]), "=r"(r[1]), "=r"(r[2]), "=r"(r[3]) : "r"(addr));
}
__device__ __forceinline__ void mma16816(float* c, const uint32_t* a, uint32_t b0, uint32_t b1) {
    asm volatile("mma.sync.aligned.m16n8k16.row.col.f32.bf16.bf16.f32 "
                 "{%0,%1,%2,%3}, {%4,%5,%6,%7}, {%8,%9}, {%0,%1,%2,%3};"
                 : "+f"(c[0]), "+f"(c[1]), "+f"(c[2]), "+f"(c[3])
                 : "r"(a[0]), "r"(a[1]), "r"(a[2]), "r"(a[3]), "r"(b0), "r"(b1));
}

// ---- acquire/release barrier primitives ----
__device__ __forceinline__ unsigned ld_acq(unsigned* p) {
    unsigned v;
    asm volatile("ld.acquire.gpu.global.u32 %0, [%1];" : "=r"(v) : "l"(p) : "memory");
    return v;
}
__device__ __forceinline__ unsigned atom_add_acqrel(unsigned* p, unsigned v) {
    unsigned old;
    asm volatile("atom.add.acq_rel.gpu.global.u32 %0, [%1], %2;" : "=r"(old) : "l"(p), "r"(v) : "memory");
    return old;
}
__device__ __forceinline__ void st_rel(unsigned* p, unsigned v) {
    asm volatile("st.release.gpu.global.u32 [%0], %1;" :: "l"(p), "r"(v) : "memory");
}
__device__ __forceinline__ void st_rlx(unsigned* p, unsigned v) {
    asm volatile("st.relaxed.gpu.global.u32 [%0], %1;" :: "l"(p), "r"(v) : "memory");
}

// grid-wide barrier, local generation counter
__device__ __forceinline__ void gbar(int nblk, unsigned& mygen) {
    __syncthreads();
    if (threadIdx.x == 0) {
        mygen++;
        if (atom_add_acqrel(&g_bar_cnt, 1u) == (unsigned)(nblk - 1)) {
            st_rlx(&g_bar_cnt, 0u);
            st_rel(&g_bar_gen, mygen);
        } else {
            while ((int)(ld_acq(&g_bar_gen) - mygen) < 0) { }
        }
    }
    __syncthreads();
}

// ---------------- K0: gather teacher-forced inputs (bf16 out) ----------------
__global__ void gather_kernel(const float* __restrict__ hidden_en,
                              const float* __restrict__ embed_w,
                              const int*   __restrict__ target) {
    const int m = blockIdx.x;
    const int l = m / BATCH, b = m % BATCH;
    const int k = threadIdx.x * 4;
    const float* src = (l == 0)
        ? (hidden_en + (size_t)b * HIDI)
        : (embed_w   + (size_t)target[b * L + (l - 1)] * HIDI);
    float4 v = *(const float4*)&src[k];
    __nv_bfloat162 a = __floats2bfloat162_rn(v.x, v.y);
    __nv_bfloat162 c = __floats2bfloat162_rn(v.z, v.w);
    *(uint2*)&g_xtsbf[(size_t)m * HIDI + k] = make_uint2(*(uint32_t*)&a, *(uint32_t*)&c);
}

// ---------------- fused weight conversions to bf16 ----------------
#define CV_WHH_Q   (G4*H/4)
#define CV_WIH_Q   (G4*HIDI/4)
#define CV_HEM_Q   (H*H/4)
#define CV_LIN_Q   (NPAD*KCAT/4)
#define CV_TOT_Q   (CV_WHH_Q + CV_WIH_Q + CV_HEM_Q + CV_LIN_Q)

__global__ void conv_all_bf(const float* __restrict__ W_hh,
                            const float* __restrict__ W_ih,
                            const float* __restrict__ hem_w,
                            const float* __restrict__ lin_w) {
    const size_t q = (size_t)blockIdx.x * 256 + threadIdx.x;
    if (q >= CV_TOT_Q) return;
    const float* src;
    __nv_bfloat16* dst;
    size_t off;
    float4 v;
    if (q < CV_WHH_Q) {
        off = q; src = W_hh; dst = g_whhbf;
        v = *(const float4*)&src[off*4];
    } else if (q < CV_WHH_Q + CV_WIH_Q) {
        off = q - CV_WHH_Q; src = W_ih; dst = g_wihbf;
        v = *(const float4*)&src[off*4];
    } else if (q < CV_WHH_Q + CV_WIH_Q + CV_HEM_Q) {
        off = q - CV_WHH_Q - CV_WIH_Q; src = hem_w; dst = g_hemwbf;
        v = *(const float4*)&src[off*4];
    } else {
        off = q - CV_WHH_Q - CV_WIH_Q - CV_HEM_Q; dst = g_linbf;
        const size_t row = (off*4) / KCAT;
        v = (row < NCLS) ? *(const float4*)&lin_w[off*4] : make_float4(0.f,0.f,0.f,0.f);
    }
    __nv_bfloat162 a = __floats2bfloat162_rn(v.x, v.y);
    __nv_bfloat162 b = __floats2bfloat162_rn(v.z, v.w);
    *(uint2*)&dst[off*4] = make_uint2(*(uint32_t*)&a, *(uint32_t*)&b);
}

// ---------------- bf16 HMMA GEMM 128x128, 8 warps (K1, K3, K5) ----------------
#define HG_LDS   40
#define HG_ROWB  80
#define HG_BUFB  (128*HG_ROWB)

__global__ void __launch_bounds__(256) hgemm_nt_bias(
        const __nv_bfloat16* __restrict__ A, int lda,
        const __nv_bfloat16* __restrict__ B, int ldb,
        const float* __restrict__ bias,
        float* __restrict__ C, int ldc,
        int nlim, int K) {
    __shared__ __nv_bfloat16 sA[2][128][HG_LDS];
    __shared__ __nv_bfloat16 sB[2][128][HG_LDS];
    const int tid  = threadIdx.x;
    const int w    = tid >> 5, lane = tid & 31;
    const int wm   = w >> 2, wn = w & 3;
    const int bm   = blockIdx.y * 128;
    const int bn   = blockIdx.x * 128;
    const int nch  = K >> 5;

    const uint32_t uA = smem_u32(&sA[0][0][0]);
    const uint32_t uB = smem_u32(&sB[0][0][0]);

    const int gr0 = tid >> 1;
    const int gs0 = tid & 1;
    const int gs1 = 2 + (tid & 1);
    const __nv_bfloat16* arow = A + (size_t)(bm + gr0) * lda;
    const __nv_bfloat16* brow = B + (size_t)(bn + gr0) * ldb;

    float acc[4][4][4];
#pragma unroll
    for (int i = 0; i < 4; i++)
#pragma unroll
        for (int j = 0; j < 4; j++)
#pragma unroll
            for (int q = 0; q < 4; q++) acc[i][j][q] = 0.0f;

    uint4 ra[2], rb[2];
    ra[0] = *(const uint4*)(arow + gs0*8);
    ra[1] = *(const uint4*)(arow + gs1*8);
    rb[0] = *(const uint4*)(brow + gs0*8);
    rb[1] = *(const uint4*)(brow + gs1*8);
    *(uint4*)((char*)&sA[0][0][0] + gr0*HG_ROWB + gs0*16) = ra[0];
    *(uint4*)((char*)&sA[0][0][0] + gr0*HG_ROWB + gs1*16) = ra[1];
    *(uint4*)((char*)&sB[0][0][0] + gr0*HG_ROWB + gs0*16) = rb[0];
    *(uint4*)((char*)&sB[0][0][0] + gr0*HG_ROWB + gs1*16) = rb[1];

    const uint32_t aoff = (uint32_t)(wm*64 + (lane & 15)) * HG_ROWB + (uint32_t)(lane >> 4) * 16;
    const uint32_t boff = (uint32_t)(wn*32 + (lane & 15)) * HG_ROWB + (uint32_t)(lane >> 4) * 16;

    for (int c = 0; c < nch; c++) {
        __syncthreads();
        if (c + 1 < nch) {
            const int k0 = (c + 1) * 32;
            ra[0] = *(const uint4*)(arow + k0 + gs0*8);
            ra[1] = *(const uint4*)(arow + k0 + gs1*8);
            rb[0] = *(const uint4*)(brow + k0 + gs0*8);
            rb[1] = *(const uint4*)(brow + k0 + gs1*8);
        }
        const uint32_t bufA = uA + (c & 1) * HG_BUFB;
        const uint32_t bufB = uB + (c & 1) * HG_BUFB;
#pragma unroll
        for (int ka = 0; ka < 2; ka++) {
            uint32_t af[4][4];
            uint32_t bf[2][4];
#pragma unroll
            for (int ma = 0; ma < 4; ma++)
                ldsm_x4(af[ma], bufA + aoff + ma*16*HG_ROWB + ka*32);
#pragma unroll
            for (int ng = 0; ng < 2; ng++)
                ldsm_x4(bf[ng], bufB + boff + ng*16*HG_ROWB + ka*32);
#pragma unroll
            for (int ma = 0; ma < 4; ma++)
#pragma unroll
                for (int ng = 0; ng < 2; ng++) {
                    mma16816(acc[ma][ng*2+0], af[ma], bf[ng][0], bf[ng][2]);
                    mma16816(acc[ma][ng*2+1], af[ma], bf[ng][1], bf[ng][3]);
                }
        }
        if (c + 1 < nch) {
            __syncthreads();
            char* dA = (char*)&sA[(c+1)&1][0][0];
            char* dB = (char*)&sB[(c+1)&1][0][0];
            *(uint4*)(dA + gr0*HG_ROWB + gs0*16) = ra[0];
            *(uint4*)(dA + gr0*HG_ROWB + gs1*16) = ra[1];
            *(uint4*)(dB + gr0*HG_ROWB + gs0*16) = rb[0];
            *(uint4*)(dB + gr0*HG_ROWB + gs1*16) = rb[1];
        }
    }

    const int g = lane >> 2, t = lane & 3;
#pragma unroll
    for (int ma = 0; ma < 4; ma++) {
        const int r0 = bm + wm*64 + ma*16 + g;
#pragma unroll
        for (int na = 0; na < 4; na++) {
            const int col = bn + wn*32 + na*8 + t*2;
            if (col + 1 < nlim) {
                const float2 bv = *(const float2*)&bias[col];
                *(float2*)&C[(size_t)r0 * ldc + col] =
                    make_float2(acc[ma][na][0] + bv.x, acc[ma][na][1] + bv.y);
                *(float2*)&C[(size_t)(r0 + 8) * ldc + col] =
                    make_float2(acc[ma][na][2] + bv.x, acc[ma][na][3] + bv.y);
            }
        }
    }
}

// ---------------- persistent LSTM: k-split 8, 256 CTAs, cheap gbar ----------------
#define LP_NBLK 256
#define LP_ROWB 144
#define LP_SMEM ((128 + 64) * LP_ROWB)

__global__ void __launch_bounds__(256) lstm_persist(const float* __restrict__ b_hh) {
    extern __shared__ char sm[];
    char* sA = sm;
    char* sB = sm + 128*LP_ROWB;
    const int tid = threadIdx.x;
    const int w = tid >> 5, lane = tid & 31;
    const int wm = w >> 2, wn = w & 3;
    const int bid = blockIdx.x;
    const int bn = (bid & 31) * 64;
    const int ks = bid >> 5;
    const uint32_t uA = smem_u32(sA), uB = smem_u32(sB);
    const int g = lane >> 2, t4 = lane & 3;

    unsigned mygen = 0;
    if (tid == 0) mygen = ld_acq(&g_bar_gen);

    for (int i = tid; i < 512; i += 256) {
        int r = i >> 3, u = i & 7;
        *(uint4*)(sB + r*LP_ROWB + u*16) =
            *(const uint4*)((const char*)(g_whhbf + (size_t)(bn + r)*H + ks*64) + u*16);
    }

    const uint32_t aoff = uA + (uint32_t)(wm*64 + (lane & 15))*LP_ROWB + (uint32_t)(lane >> 4)*16;
    const uint32_t boff = uB + (uint32_t)(wn*16 + (lane & 15))*LP_ROWB + (uint32_t)(lane >> 4)*16;

    for (int l = 0; l < L; l++) {
        if (l > 0) {
            for (int i = tid; i < 1024; i += 256) {
                int r = i >> 3, u = i & 7;
                *(uint4*)(sA + r*LP_ROWB + u*16) =
                    *(const uint4*)((const char*)(g_catbf + (size_t)((l-1)*BATCH + r)*KCAT + ks*64) + u*16);
            }
            __syncthreads();
            float acc[4][2][4];
#pragma unroll
            for (int ma = 0; ma < 4; ma++)
#pragma unroll
                for (int na = 0; na < 2; na++)
#pragma unroll
                    for (int q = 0; q < 4; q++) acc[ma][na][q] = 0.0f;
#pragma unroll
            for (int ka = 0; ka < 4; ka++) {
                uint32_t af[4][4], bfr[4];
#pragma unroll
                for (int ma = 0; ma < 4; ma++)
                    ldsm_x4(af[ma], aoff + ma*16*LP_ROWB + ka*32);
                ldsm_x4(bfr, boff + ka*32);
#pragma unroll
                for (int ma = 0; ma < 4; ma++) {
                    mma16816(acc[ma][0], af[ma], bfr[0], bfr[2]);
                    mma16816(acc[ma][1], af[ma], bfr[1], bfr[3]);
                }
            }
#pragma unroll
            for (int ma = 0; ma < 4; ma++) {
                const int r0 = wm*64 + ma*16 + g;
#pragma unroll
                for (int na = 0; na < 2; na++) {
                    const int col = bn + wn*16 + na*8 + t4*2;
                    *(float2*)&g_part[((size_t)ks*BATCH + r0)*G4 + col] =
                        make_float2(acc[ma][na][0], acc[ma][na][1]);
                    *(float2*)&g_part[((size_t)ks*BATCH + r0 + 8)*G4 + col] =
                        make_float2(acc[ma][na][2], acc[ma][na][3]);
                }
            }
            gbar(LP_NBLK, mygen);
        }
        {
            const int e0 = bid*256 + tid;
            const int b = e0 >> 9, d = e0 & 511;
            float gv[4];
#pragma unroll
            for (int q = 0; q < 4; q++) {
                const int n = q*H + d;
                float v = g_xg[(size_t)(l*BATCH + b)*G4 + n] + b_hh[n];
                if (l > 0) {
#pragma unroll
                    for (int s = 0; s < 8; s++)
                        v += g_part[((size_t)s*BATCH + b)*G4 + n];
                }
                gv[q] = v;
            }
            float cp = (l > 0) ? g_c[b*H + d] : 0.0f;
            float ig = sigmoid_acc(gv[0]);
            float fg = sigmoid_acc(gv[1]);
            float gg = tanhf(gv[2]);
            float og = sigmoid_acc(gv[3]);
            float cn = fg*cp + ig*gg;
            g_c[b*H + d] = cn;
            g_catbf[(size_t)(l*BATCH + b)*KCAT + d] = __float2bfloat16(og * tanhf(cn));
        }
        if (l + 1 < L) gbar(LP_NBLK, mygen);
    }
}

// ---------------- K4a ----------------
__global__ void featatt_kernel(const float* __restrict__ x_em,
                               const float* __restrict__ attw_w,
                               const float* __restrict__ attw_b) {
    __shared__ float sx[512][17];
    __shared__ float sh_hem[512];
    __shared__ float sh_w[512];
    __shared__ float red[16][17];
    const int tid = threadIdx.x;
    const int b  = blockIdx.y;
    const int n0 = blockIdx.x * 16;
#pragma unroll
    for (int i = 0; i < 32; i++) {
        int e = tid + i*256;
        int c = e >> 4, j = e & 15;
        sx[c][j] = x_em[((size_t)b*512 + c) * 256 + n0 + j];
    }
    sh_w[tid]     = attw_w[tid];
    sh_w[tid+256] = attw_w[tid+256];
    const float ab = attw_b[0];
    const int j  = tid % 16;
    const int cg = tid / 16;
    for (int l = 0; l < L; l++) {
        __syncthreads();
        sh_hem[tid]     = g_hem[(size_t)(l*BATCH + b) * H + tid];
        sh_hem[tid+256] = g_hem[(size_t)(l*BATCH + b) * H + tid + 256];
        __syncthreads();
        float acc = 0.0f;
#pragma unroll 8
        for (int i = 0; i < 32; i++) {
            int c = cg*32 + i;
            acc += tanh_approx(sx[c][j] + sh_hem[c]) * sh_w[c];
        }
        red[cg][j] = acc;
        __syncthreads();
        if (tid < 16) {
            float s = 0.0f;
#pragma unroll
            for (int i = 0; i < 16; i++) s += red[i][tid];
            g_fatt[(size_t)(l*BATCH + b) * HW + n0 + tid] = s + ab;
        }
    }
}

// ---------------- K4b ----------------
__global__ void attred_kernel(const float* __restrict__ att_x_em) {
    __shared__ float s_alpha[L][HW];
    __shared__ float s_red[8];
    __shared__ float s_val;
    const int tid = threadIdx.x;
    const int b = blockIdx.x;
    const int lane = tid & 31, wid = tid >> 5;
    for (int l = 0; l < L; l++) {
        float v = g_fatt[(size_t)(l*BATCH + b) * HW + tid];
        float m = v;
#pragma unroll
        for (int o = 16; o > 0; o >>= 1) m = fmaxf(m, __shfl_xor_sync(~0u, m, o));
        if (lane == 0) s_red[wid] = m;
        __syncthreads();
        if (tid == 0) {
            float mm = s_red[0];
#pragma unroll
            for (int i = 1; i < 8; i++) mm = fmaxf(mm, s_red[i]);
            s_val = mm;
        }
        __syncthreads();
        float e = __expf(v - s_val);
        float s = e;
#pragma unroll
        for (int o = 16; o > 0; o >>= 1) s += __shfl_xor_sync(~0u, s, o);
        if (lane == 0) s_red[wid] = s;
        __syncthreads();
        if (tid == 0) {
            float ss = 0.0f;
#pragma unroll
            for (int i = 0; i < 8; i++) ss += s_red[i];
            s_val = ss;
        }
        __syncthreads();
        s_alpha[l][tid] = e / s_val;
        __syncthreads();
    }
    float acc[L][2];
#pragma unroll
    for (int l = 0; l < L; l++) { acc[l][0] = 0.0f; acc[l][1] = 0.0f; }
    const float* axb = att_x_em + (size_t)b * HW * H;
    for (int n = 0; n < HW; n++) {
        float2 ax = *(const float2*)&axb[(size_t)n * H + 2*tid];
#pragma unroll
        for (int l = 0; l < L; l++) {
            float a = s_alpha[l][n];
            acc[l][0] += a * ax.x;
            acc[l][1] += a * ax.y;
        }
    }
#pragma unroll
    for (int l = 0; l < L; l++) {
        __nv_bfloat162 ab2 = __floats2bfloat162_rn(acc[l][0], acc[l][1]);
        *(uint32_t*)&g_catbf[(size_t)(l*BATCH + b)*KCAT + 512 + 2*tid] = *(uint32_t*)&ab2;
    }
}

// ---------------- K6: row log-softmax ----------------
__global__ void logsoftmax_kernel(float* __restrict__ out) {
    const int m = blockIdx.x;
    const int l = m / BATCH, b = m % BATCH;
    const int tid = threadIdx.x;
    const int lane = tid & 31, wid = tid >> 5;
    __shared__ float s_red[8];
    __shared__ float s_val;
    float4 vals[7];
    const float4* row = (const float4*)(g_logits + (size_t)m * NCLS);
#pragma unroll
    for (int i = 0; i < 7; i++) {
        int idx = tid + i*256;
        vals[i] = (idx < NCLS/4) ? row[idx] : make_float4(-1e30f,-1e30f,-1e30f,-1e30f);
    }
    float mx = -1e30f;
#pragma unroll
    for (int i = 0; i < 7; i++) {
        mx = fmaxf(mx, fmaxf(fmaxf(vals[i].x, vals[i].y), fmaxf(vals[i].z, vals[i].w)));
    }
#pragma unroll
    for (int o = 16; o > 0; o >>= 1) mx = fmaxf(mx, __shfl_xor_sync(~0u, mx, o));
    if (lane == 0) s_red[wid] = mx;
    __syncthreads();
    if (tid == 0) {
        float mm = s_red[0];
#pragma unroll
        for (int i = 1; i < 8; i++) mm = fmaxf(mm, s_red[i]);
        s_val = mm;
    }
    __syncthreads();
    const float mall = s_val;
    float sum = 0.0f;
#pragma unroll
    for (int i = 0; i < 7; i++) {
        sum += __expf(vals[i].x - mall) + __expf(vals[i].y - mall)
             + __expf(vals[i].z - mall) + __expf(vals[i].w - mall);
    }
#pragma unroll
    for (int o = 16; o > 0; o >>= 1) sum += __shfl_xor_sync(~0u, sum, o);
    if (lane == 0) s_red[wid] = sum;
    __syncthreads();
    if (tid == 0) {
        float ss = 0.0f;
#pragma unroll
        for (int i = 0; i < 8; i++) ss += s_red[i];
        s_val = ss;
    }
    __syncthreads();
    const float lse = mall + logf(s_val);
    float4* orow = (float4*)(out + ((size_t)b * L + l) * NCLS);
#pragma unroll
    for (int i = 0; i < 7; i++) {
        int idx = tid + i*256;
        if (idx < NCLS/4) {
            float4 v = vals[i];
            orow[idx] = make_float4(v.x - lse, v.y - lse, v.z - lse, v.w - lse);
        }
    }
}

// ---------------- launch ----------------
extern "C" void kernel_launch(void* const* d_in, const int* in_sizes, int n_in,
                              void* d_out, int out_size) {
    const float* hidden_en = (const float*)d_in[0];
    const float* x_em      = (const float*)d_in[1];
    const float* att_x_em  = (const float*)d_in[2];
    const int*   target    = (const int*)  d_in[3];
    const float* embed_w = (const float*)d_in[6];
    const float* W_ih    = (const float*)d_in[7];
    const float* W_hh    = (const float*)d_in[8];
    const float* b_ih    = (const float*)d_in[9];
    const float* b_hh    = (const float*)d_in[10];
    const float* hem_w   = (const float*)d_in[11];
    const float* hem_b   = (const float*)d_in[12];
    const float* attw_w  = (const float*)d_in[13];
    const float* attw_b  = (const float*)d_in[14];
    const float* lin_w   = (const float*)d_in[15];
    const float* lin_b   = (const float*)d_in[16];
    float* out = (float*)d_out;

    void *p_xg, *p_hem, *p_xtsbf, *p_catbf, *p_linbf, *p_whhbf, *p_wihbf, *p_hemwbf, *p_logits;
    cudaGetSymbolAddress(&p_xg,     g_xg);
    cudaGetSymbolAddress(&p_hem,    g_hem);
    cudaGetSymbolAddress(&p_xtsbf,  g_xtsbf);
    cudaGetSymbolAddress(&p_catbf,  g_catbf);
    cudaGetSymbolAddress(&p_linbf,  g_linbf);
    cudaGetSymbolAddress(&p_whhbf,  g_whhbf);
    cudaGetSymbolAddress(&p_wihbf,  g_wihbf);
    cudaGetSymbolAddress(&p_hemwbf, g_hemwbf);
    cudaGetSymbolAddress(&p_logits, g_logits);

    cudaFuncSetAttribute(lstm_persist, cudaFuncAttributeMaxDynamicSharedMemorySize, LP_SMEM);

    // 1: gather (bf16 out)
    gather_kernel<<<M5, 128>>>(hidden_en, embed_w, target);

    // 2: fused weight conversions
    conv_all_bf<<<(CV_TOT_Q + 255)/256, 256>>>(W_hh, W_ih, hem_w, lin_w);

    // 3: K1  xg = xts @ W_ih^T + b_ih
    hgemm_nt_bias<<<dim3(G4/128, M5/128), 256>>>(
        (const __nv_bfloat16*)p_xtsbf, HIDI, (const __nv_bfloat16*)p_wihbf, HIDI,
        b_ih, (float*)p_xg, G4, G4, HIDI);

    // 4: persistent LSTM
    lstm_persist<<<LP_NBLK, 256, LP_SMEM>>>(b_hh);

    // 5: K3  hem = h @ hem_w^T + hem_b
    hgemm_nt_bias<<<dim3(H/128, M5/128), 256>>>(
        (const __nv_bfloat16*)p_catbf, KCAT, (const __nv_bfloat16*)p_hemwbf, H,
        hem_b, (float*)p_hem, H, H, H);

    // 6: featatt
    featatt_kernel<<<dim3(16, BATCH), 256>>>(x_em, attw_w, attw_b);

    // 7: attred
    attred_kernel<<<BATCH, 256>>>(att_x_em);

    // 8: K5  logits (8-warp kernel — best measured)
    hgemm_nt_bias<<<dim3(NPAD/128, M5/128), 256>>>(
        (const __nv_bfloat16*)p_catbf, KCAT, (const __nv_bfloat16*)p_linbf, KCAT,
        lin_b, (float*)p_logits, NCLS, NCLS, KCAT);

    // 9: K6
    logsoftmax_kernel<<<M5, 256>>>(out);
}

// round 17
// speedup vs baseline: 1.4539x; 1.4539x over previous
#include <cuda_runtime.h>
#include <cuda_bf16.h>
#include <math.h>
#include <cstdint>

#define L      40
#define BATCH  128
#define HIDI   512
#define H      512
#define G4     2048
#define NCLS   7000
#define NPAD   7040
#define HW     256
#define M5     (L*BATCH)   /* 5120 */
#define KCAT   1024

// ---------------- scratch (static device globals: no allocation) ----------------
__device__ float g_xg [M5*G4];
__device__ float g_hem[M5*H];
__device__ float g_fatt[M5*HW];
__device__ float g_part[8*BATCH*G4];
__device__ float g_logits[(size_t)M5*NCLS];
__device__ __nv_bfloat16 g_xtsbf[M5*HIDI];
__device__ __nv_bfloat16 g_catbf[(size_t)M5*KCAT];   // h | att, bf16
__device__ __nv_bfloat16 g_linbf[(size_t)NPAD*KCAT];
__device__ __nv_bfloat16 g_whhbf[G4*H];
__device__ __nv_bfloat16 g_wihbf[G4*HIDI];
__device__ __nv_bfloat16 g_hemwbf[H*H];
__device__ unsigned int g_bar_cnt;
__device__ unsigned int g_bar_gen;

__device__ __forceinline__ float tanh_approx(float x) {
    float y; asm("tanh.approx.f32 %0, %1;" : "=f"(y) : "f"(x)); return y;
}
__device__ __forceinline__ float sigmoid_acc(float x) { return 1.0f / (1.0f + expf(-x)); }

__device__ __forceinline__ uint32_t smem_u32(const void* p) {
    uint32_t a;
    asm("{ .reg .u64 t; cvta.to.shared.u64 t, %1; cvt.u32.u64 %0, t; }" : "=r"(a) : "l"(p));
    return a;
}
__device__ __forceinline__ void ldsm_x4(uint32_t* r, uint32_t addr) {
    asm volatile("ldmatrix.sync.aligned.m8n8.x4.shared.b16 {%0,%1,%2,%3}, [%4];"
                 : "=r"(r[0]), "=r"(r[1]), "=r"(r[2]), "=r"(r[3]) : "r"(addr));
}
__device__ __forceinline__ void mma16816(float* c, const uint32_t* a, uint32_t b0, uint32_t b1) {
    asm volatile("mma.sync.aligned.m16n8k16.row.col.f32.bf16.bf16.f32 "
                 "{%0,%1,%2,%3}, {%4,%5,%6,%7}, {%8,%9}, {%0,%1,%2,%3};"
                 : "+f"(c[0]), "+f"(c[1]), "+f"(c[2]), "+f"(c[3])
                 : "r"(a[0]), "r"(a[1]), "r"(a[2]), "r"(a[3]), "r"(b0), "r"(b1));
}

// ---- acquire/release barrier primitives ----
__device__ __forceinline__ unsigned ld_acq(unsigned* p) {
    unsigned v;
    asm volatile("ld.acquire.gpu.global.u32 %0, [%1];" : "=r"(v) : "l"(p) : "memory");
    return v;
}
__device__ __forceinline__ unsigned atom_add_acqrel(unsigned* p, unsigned v) {
    unsigned old;
    asm volatile("atom.add.acq_rel.gpu.global.u32 %0, [%1], %2;" : "=r"(old) : "l"(p), "r"(v) : "memory");
    return old;
}
__device__ __forceinline__ void st_rel(unsigned* p, unsigned v) {
    asm volatile("st.release.gpu.global.u32 [%0], %1;" :: "l"(p), "r"(v) : "memory");
}
__device__ __forceinline__ void st_rlx(unsigned* p, unsigned v) {
    asm volatile("st.relaxed.gpu.global.u32 [%0], %1;" :: "l"(p), "r"(v) : "memory");
}

// grid-wide barrier, local generation counter
__device__ __forceinline__ void gbar(int nblk, unsigned& mygen) {
    __syncthreads();
    if (threadIdx.x == 0) {
        mygen++;
        if (atom_add_acqrel(&g_bar_cnt, 1u) == (unsigned)(nblk - 1)) {
            st_rlx(&g_bar_cnt, 0u);
            st_rel(&g_bar_gen, mygen);
        } else {
            while ((int)(ld_acq(&g_bar_gen) - mygen) < 0) { }
        }
    }
    __syncthreads();
}

// ---------------- K0: gather teacher-forced inputs (bf16 out) ----------------
__global__ void gather_kernel(const float* __restrict__ hidden_en,
                              const float* __restrict__ embed_w,
                              const int*   __restrict__ target) {
    const int m = blockIdx.x;
    const int l = m / BATCH, b = m % BATCH;
    const int k = threadIdx.x * 4;
    const float* src = (l == 0)
        ? (hidden_en + (size_t)b * HIDI)
        : (embed_w   + (size_t)target[b * L + (l - 1)] * HIDI);
    float4 v = *(const float4*)&src[k];
    __nv_bfloat162 a = __floats2bfloat162_rn(v.x, v.y);
    __nv_bfloat162 c = __floats2bfloat162_rn(v.z, v.w);
    *(uint2*)&g_xtsbf[(size_t)m * HIDI + k] = make_uint2(*(uint32_t*)&a, *(uint32_t*)&c);
}

// ---------------- fused weight conversions to bf16 ----------------
#define CV_WHH_Q   (G4*H/4)
#define CV_WIH_Q   (G4*HIDI/4)
#define CV_HEM_Q   (H*H/4)
#define CV_LIN_Q   (NPAD*KCAT/4)
#define CV_TOT_Q   (CV_WHH_Q + CV_WIH_Q + CV_HEM_Q + CV_LIN_Q)

__global__ void conv_all_bf(const float* __restrict__ W_hh,
                            const float* __restrict__ W_ih,
                            const float* __restrict__ hem_w,
                            const float* __restrict__ lin_w) {
    const size_t q = (size_t)blockIdx.x * 256 + threadIdx.x;
    if (q >= CV_TOT_Q) return;
    const float* src;
    __nv_bfloat16* dst;
    size_t off;
    float4 v;
    if (q < CV_WHH_Q) {
        off = q; src = W_hh; dst = g_whhbf;
        v = *(const float4*)&src[off*4];
    } else if (q < CV_WHH_Q + CV_WIH_Q) {
        off = q - CV_WHH_Q; src = W_ih; dst = g_wihbf;
        v = *(const float4*)&src[off*4];
    } else if (q < CV_WHH_Q + CV_WIH_Q + CV_HEM_Q) {
        off = q - CV_WHH_Q - CV_WIH_Q; src = hem_w; dst = g_hemwbf;
        v = *(const float4*)&src[off*4];
    } else {
        off = q - CV_WHH_Q - CV_WIH_Q - CV_HEM_Q; dst = g_linbf;
        const size_t row = (off*4) / KCAT;
        v = (row < NCLS) ? *(const float4*)&lin_w[off*4] : make_float4(0.f,0.f,0.f,0.f);
    }
    __nv_bfloat162 a = __floats2bfloat162_rn(v.x, v.y);
    __nv_bfloat162 b = __floats2bfloat162_rn(v.z, v.w);
    *(uint2*)&dst[off*4] = make_uint2(*(uint32_t*)&a, *(uint32_t*)&b);
}

// ---------------- bf16 HMMA GEMM 128x128, 8 warps (K1, K3, K5) ----------------
#define HG_LDS   40
#define HG_ROWB  80
#define HG_BUFB  (128*HG_ROWB)

__global__ void __launch_bounds__(256) hgemm_nt_bias(
        const __nv_bfloat16* __restrict__ A, int lda,
        const __nv_bfloat16* __restrict__ B, int ldb,
        const float* __restrict__ bias,
        float* __restrict__ C, int ldc,
        int nlim, int K) {
    __shared__ __nv_bfloat16 sA[2][128][HG_LDS];
    __shared__ __nv_bfloat16 sB[2][128][HG_LDS];
    const int tid  = threadIdx.x;
    const int w    = tid >> 5, lane = tid & 31;
    const int wm   = w >> 2, wn = w & 3;
    const int bm   = blockIdx.y * 128;
    const int bn   = blockIdx.x * 128;
    const int nch  = K >> 5;

    const uint32_t uA = smem_u32(&sA[0][0][0]);
    const uint32_t uB = smem_u32(&sB[0][0][0]);

    const int gr0 = tid >> 1;
    const int gs0 = tid & 1;
    const int gs1 = 2 + (tid & 1);
    const __nv_bfloat16* arow = A + (size_t)(bm + gr0) * lda;
    const __nv_bfloat16* brow = B + (size_t)(bn + gr0) * ldb;

    float acc[4][4][4];
#pragma unroll
    for (int i = 0; i < 4; i++)
#pragma unroll
        for (int j = 0; j < 4; j++)
#pragma unroll
            for (int q = 0; q < 4; q++) acc[i][j][q] = 0.0f;

    uint4 ra[2], rb[2];
    ra[0] = *(const uint4*)(arow + gs0*8);
    ra[1] = *(const uint4*)(arow + gs1*8);
    rb[0] = *(const uint4*)(brow + gs0*8);
    rb[1] = *(const uint4*)(brow + gs1*8);
    *(uint4*)((char*)&sA[0][0][0] + gr0*HG_ROWB + gs0*16) = ra[0];
    *(uint4*)((char*)&sA[0][0][0] + gr0*HG_ROWB + gs1*16) = ra[1];
    *(uint4*)((char*)&sB[0][0][0] + gr0*HG_ROWB + gs0*16) = rb[0];
    *(uint4*)((char*)&sB[0][0][0] + gr0*HG_ROWB + gs1*16) = rb[1];

    const uint32_t aoff = (uint32_t)(wm*64 + (lane & 15)) * HG_ROWB + (uint32_t)(lane >> 4) * 16;
    const uint32_t boff = (uint32_t)(wn*32 + (lane & 15)) * HG_ROWB + (uint32_t)(lane >> 4) * 16;

    for (int c = 0; c < nch; c++) {
        __syncthreads();
        if (c + 1 < nch) {
            const int k0 = (c + 1) * 32;
            ra[0] = *(const uint4*)(arow + k0 + gs0*8);
            ra[1] = *(const uint4*)(arow + k0 + gs1*8);
            rb[0] = *(const uint4*)(brow + k0 + gs0*8);
            rb[1] = *(const uint4*)(brow + k0 + gs1*8);
        }
        const uint32_t bufA = uA + (c & 1) * HG_BUFB;
        const uint32_t bufB = uB + (c & 1) * HG_BUFB;
#pragma unroll
        for (int ka = 0; ka < 2; ka++) {
            uint32_t af[4][4];
            uint32_t bf[2][4];
#pragma unroll
            for (int ma = 0; ma < 4; ma++)
                ldsm_x4(af[ma], bufA + aoff + ma*16*HG_ROWB + ka*32);
#pragma unroll
            for (int ng = 0; ng < 2; ng++)
                ldsm_x4(bf[ng], bufB + boff + ng*16*HG_ROWB + ka*32);
#pragma unroll
            for (int ma = 0; ma < 4; ma++)
#pragma unroll
                for (int ng = 0; ng < 2; ng++) {
                    mma16816(acc[ma][ng*2+0], af[ma], bf[ng][0], bf[ng][2]);
                    mma16816(acc[ma][ng*2+1], af[ma], bf[ng][1], bf[ng][3]);
                }
        }
        if (c + 1 < nch) {
            __syncthreads();
            char* dA = (char*)&sA[(c+1)&1][0][0];
            char* dB = (char*)&sB[(c+1)&1][0][0];
            *(uint4*)(dA + gr0*HG_ROWB + gs0*16) = ra[0];
            *(uint4*)(dA + gr0*HG_ROWB + gs1*16) = ra[1];
            *(uint4*)(dB + gr0*HG_ROWB + gs0*16) = rb[0];
            *(uint4*)(dB + gr0*HG_ROWB + gs1*16) = rb[1];
        }
    }

    const int g = lane >> 2, t = lane & 3;
#pragma unroll
    for (int ma = 0; ma < 4; ma++) {
        const int r0 = bm + wm*64 + ma*16 + g;
#pragma unroll
        for (int na = 0; na < 4; na++) {
            const int col = bn + wn*32 + na*8 + t*2;
            if (col + 1 < nlim) {
                const float2 bv = *(const float2*)&bias[col];
                *(float2*)&C[(size_t)r0 * ldc + col] =
                    make_float2(acc[ma][na][0] + bv.x, acc[ma][na][1] + bv.y);
                *(float2*)&C[(size_t)(r0 + 8) * ldc + col] =
                    make_float2(acc[ma][na][2] + bv.x, acc[ma][na][3] + bv.y);
            }
        }
    }
}

// ---------------- persistent LSTM: k-split 8, 256 CTAs, registerized c ----------------
#define LP_NBLK 256
#define LP_ROWB 144
#define LP_SMEM ((128 + 64) * LP_ROWB)

__global__ void __launch_bounds__(256) lstm_persist(const float* __restrict__ b_hh) {
    extern __shared__ char sm[];
    char* sA = sm;
    char* sB = sm + 128*LP_ROWB;
    const int tid = threadIdx.x;
    const int w = tid >> 5, lane = tid & 31;
    const int wm = w >> 2, wn = w & 3;
    const int bid = blockIdx.x;
    const int bn = (bid & 31) * 64;
    const int ks = bid >> 5;
    const uint32_t uA = smem_u32(sA), uB = smem_u32(sB);
    const int g = lane >> 2, t4 = lane & 3;

    unsigned mygen = 0;
    if (tid == 0) mygen = ld_acq(&g_bar_gen);

    // this thread's pointwise element (fixed across steps)
    const int e0 = bid*256 + tid;
    const int pb = e0 >> 9, pd = e0 & 511;
    float c_reg = 0.0f;                        // registerized cell state
    float bh[4];                               // hoisted biases
#pragma unroll
    for (int q = 0; q < 4; q++) bh[q] = b_hh[q*H + pd];

    for (int i = tid; i < 512; i += 256) {
        int r = i >> 3, u = i & 7;
        *(uint4*)(sB + r*LP_ROWB + u*16) =
            *(const uint4*)((const char*)(g_whhbf + (size_t)(bn + r)*H + ks*64) + u*16);
    }

    const uint32_t aoff = uA + (uint32_t)(wm*64 + (lane & 15))*LP_ROWB + (uint32_t)(lane >> 4)*16;
    const uint32_t boff = uB + (uint32_t)(wn*16 + (lane & 15))*LP_ROWB + (uint32_t)(lane >> 4)*16;

    for (int l = 0; l < L; l++) {
        // xg prefetch: depends only on l, issues before barrier/partials
        float xg[4];
#pragma unroll
        for (int q = 0; q < 4; q++)
            xg[q] = g_xg[(size_t)(l*BATCH + pb)*G4 + q*H + pd];

        if (l > 0) {
            for (int i = tid; i < 1024; i += 256) {
                int r = i >> 3, u = i & 7;
                *(uint4*)(sA + r*LP_ROWB + u*16) =
                    *(const uint4*)((const char*)(g_catbf + (size_t)((l-1)*BATCH + r)*KCAT + ks*64) + u*16);
            }
            __syncthreads();
            float acc[4][2][4];
#pragma unroll
            for (int ma = 0; ma < 4; ma++)
#pragma unroll
                for (int na = 0; na < 2; na++)
#pragma unroll
                    for (int q = 0; q < 4; q++) acc[ma][na][q] = 0.0f;
#pragma unroll
            for (int ka = 0; ka < 4; ka++) {
                uint32_t af[4][4], bfr[4];
#pragma unroll
                for (int ma = 0; ma < 4; ma++)
                    ldsm_x4(af[ma], aoff + ma*16*LP_ROWB + ka*32);
                ldsm_x4(bfr, boff + ka*32);
#pragma unroll
                for (int ma = 0; ma < 4; ma++) {
                    mma16816(acc[ma][0], af[ma], bfr[0], bfr[2]);
                    mma16816(acc[ma][1], af[ma], bfr[1], bfr[3]);
                }
            }
#pragma unroll
            for (int ma = 0; ma < 4; ma++) {
                const int r0 = wm*64 + ma*16 + g;
#pragma unroll
                for (int na = 0; na < 2; na++) {
                    const int col = bn + wn*16 + na*8 + t4*2;
                    *(float2*)&g_part[((size_t)ks*BATCH + r0)*G4 + col] =
                        make_float2(acc[ma][na][0], acc[ma][na][1]);
                    *(float2*)&g_part[((size_t)ks*BATCH + r0 + 8)*G4 + col] =
                        make_float2(acc[ma][na][2], acc[ma][na][3]);
                }
            }
            gbar(LP_NBLK, mygen);
        }
        // pointwise: only partial loads are post-barrier dependent
        {
            float gv[4];
#pragma unroll
            for (int q = 0; q < 4; q++) {
                float v = xg[q] + bh[q];
                if (l > 0) {
                    const int n = q*H + pd;
#pragma unroll
                    for (int s = 0; s < 8; s++)
                        v += g_part[((size_t)s*BATCH + pb)*G4 + n];
                }
                gv[q] = v;
            }
            float ig = sigmoid_acc(gv[0]);
            float fg = sigmoid_acc(gv[1]);
            float gg = tanhf(gv[2]);
            float og = sigmoid_acc(gv[3]);
            float cn = fg*c_reg + ig*gg;
            c_reg = cn;
            g_catbf[(size_t)(l*BATCH + pb)*KCAT + pd] = __float2bfloat16(og * tanhf(cn));
        }
        if (l + 1 < L) gbar(LP_NBLK, mygen);
    }
}

// ---------------- K4a ----------------
__global__ void featatt_kernel(const float* __restrict__ x_em,
                               const float* __restrict__ attw_w,
                               const float* __restrict__ attw_b) {
    __shared__ float sx[512][17];
    __shared__ float sh_hem[512];
    __shared__ float sh_w[512];
    __shared__ float red[16][17];
    const int tid = threadIdx.x;
    const int b  = blockIdx.y;
    const int n0 = blockIdx.x * 16;
#pragma unroll
    for (int i = 0; i < 32; i++) {
        int e = tid + i*256;
        int c = e >> 4, j = e & 15;
        sx[c][j] = x_em[((size_t)b*512 + c) * 256 + n0 + j];
    }
    sh_w[tid]     = attw_w[tid];
    sh_w[tid+256] = attw_w[tid+256];
    const float ab = attw_b[0];
    const int j  = tid % 16;
    const int cg = tid / 16;
    for (int l = 0; l < L; l++) {
        __syncthreads();
        sh_hem[tid]     = g_hem[(size_t)(l*BATCH + b) * H + tid];
        sh_hem[tid+256] = g_hem[(size_t)(l*BATCH + b) * H + tid + 256];
        __syncthreads();
        float acc = 0.0f;
#pragma unroll 8
        for (int i = 0; i < 32; i++) {
            int c = cg*32 + i;
            acc += tanh_approx(sx[c][j] + sh_hem[c]) * sh_w[c];
        }
        red[cg][j] = acc;
        __syncthreads();
        if (tid < 16) {
            float s = 0.0f;
#pragma unroll
            for (int i = 0; i < 16; i++) s += red[i][tid];
            g_fatt[(size_t)(l*BATCH + b) * HW + n0 + tid] = s + ab;
        }
    }
}

// ---------------- K4b ----------------
__global__ void attred_kernel(const float* __restrict__ att_x_em) {
    __shared__ float s_alpha[L][HW];
    __shared__ float s_red[8];
    __shared__ float s_val;
    const int tid = threadIdx.x;
    const int b = blockIdx.x;
    const int lane = tid & 31, wid = tid >> 5;
    for (int l = 0; l < L; l++) {
        float v = g_fatt[(size_t)(l*BATCH + b) * HW + tid];
        float m = v;
#pragma unroll
        for (int o = 16; o > 0; o >>= 1) m = fmaxf(m, __shfl_xor_sync(~0u, m, o));
        if (lane == 0) s_red[wid] = m;
        __syncthreads();
        if (tid == 0) {
            float mm = s_red[0];
#pragma unroll
            for (int i = 1; i < 8; i++) mm = fmaxf(mm, s_red[i]);
            s_val = mm;
        }
        __syncthreads();
        float e = __expf(v - s_val);
        float s = e;
#pragma unroll
        for (int o = 16; o > 0; o >>= 1) s += __shfl_xor_sync(~0u, s, o);
        if (lane == 0) s_red[wid] = s;
        __syncthreads();
        if (tid == 0) {
            float ss = 0.0f;
#pragma unroll
            for (int i = 0; i < 8; i++) ss += s_red[i];
            s_val = ss;
        }
        __syncthreads();
        s_alpha[l][tid] = e / s_val;
        __syncthreads();
    }
    float acc[L][2];
#pragma unroll
    for (int l = 0; l < L; l++) { acc[l][0] = 0.0f; acc[l][1] = 0.0f; }
    const float* axb = att_x_em + (size_t)b * HW * H;
    for (int n = 0; n < HW; n++) {
        float2 ax = *(const float2*)&axb[(size_t)n * H + 2*tid];
#pragma unroll
        for (int l = 0; l < L; l++) {
            float a = s_alpha[l][n];
            acc[l][0] += a * ax.x;
            acc[l][1] += a * ax.y;
        }
    }
#pragma unroll
    for (int l = 0; l < L; l++) {
        __nv_bfloat162 ab2 = __floats2bfloat162_rn(acc[l][0], acc[l][1]);
        *(uint32_t*)&g_catbf[(size_t)(l*BATCH + b)*KCAT + 512 + 2*tid] = *(uint32_t*)&ab2;
    }
}

// ---------------- K6: row log-softmax ----------------
__global__ void logsoftmax_kernel(float* __restrict__ out) {
    const int m = blockIdx.x;
    const int l = m / BATCH, b = m % BATCH;
    const int tid = threadIdx.x;
    const int lane = tid & 31, wid = tid >> 5;
    __shared__ float s_red[8];
    __shared__ float s_val;
    float4 vals[7];
    const float4* row = (const float4*)(g_logits + (size_t)m * NCLS);
#pragma unroll
    for (int i = 0; i < 7; i++) {
        int idx = tid + i*256;
        vals[i] = (idx < NCLS/4) ? row[idx] : make_float4(-1e30f,-1e30f,-1e30f,-1e30f);
    }
    float mx = -1e30f;
#pragma unroll
    for (int i = 0; i < 7; i++) {
        mx = fmaxf(mx, fmaxf(fmaxf(vals[i].x, vals[i].y), fmaxf(vals[i].z, vals[i].w)));
    }
#pragma unroll
    for (int o = 16; o > 0; o >>= 1) mx = fmaxf(mx, __shfl_xor_sync(~0u, mx, o));
    if (lane == 0) s_red[wid] = mx;
    __syncthreads();
    if (tid == 0) {
        float mm = s_red[0];
#pragma unroll
        for (int i = 1; i < 8; i++) mm = fmaxf(mm, s_red[i]);
        s_val = mm;
    }
    __syncthreads();
    const float mall = s_val;
    float sum = 0.0f;
#pragma unroll
    for (int i = 0; i < 7; i++) {
        sum += __expf(vals[i].x - mall) + __expf(vals[i].y - mall)
             + __expf(vals[i].z - mall) + __expf(vals[i].w - mall);
    }
#pragma unroll
    for (int o = 16; o > 0; o >>= 1) sum += __shfl_xor_sync(~0u, sum, o);
    if (lane == 0) s_red[wid] = sum;
    __syncthreads();
    if (tid == 0) {
        float ss = 0.0f;
#pragma unroll
        for (int i = 0; i < 8; i++) ss += s_red[i];
        s_val = ss;
    }
    __syncthreads();
    const float lse = mall + logf(s_val);
    float4* orow = (float4*)(out + ((size_t)b * L + l) * NCLS);
#pragma unroll
    for (int i = 0; i < 7; i++) {
        int idx = tid + i*256;
        if (idx < NCLS/4) {
            float4 v = vals[i];
            orow[idx] = make_float4(v.x - lse, v.y - lse, v.z - lse, v.w - lse);
        }
    }
}

// ---------------- launch ----------------
extern "C" void kernel_launch(void* const* d_in, const int* in_sizes, int n_in,
                              void* d_out, int out_size) {
    const float* hidden_en = (const float*)d_in[0];
    const float* x_em      = (const float*)d_in[1];
    const float* att_x_em  = (const float*)d_in[2];
    const int*   target    = (const int*)  d_in[3];
    const float* embed_w = (const float*)d_in[6];
    const float* W_ih    = (const float*)d_in[7];
    const float* W_hh    = (const float*)d_in[8];
    const float* b_ih    = (const float*)d_in[9];
    const float* b_hh    = (const float*)d_in[10];
    const float* hem_w   = (const float*)d_in[11];
    const float* hem_b   = (const float*)d_in[12];
    const float* attw_w  = (const float*)d_in[13];
    const float* attw_b  = (const float*)d_in[14];
    const float* lin_w   = (const float*)d_in[15];
    const float* lin_b   = (const float*)d_in[16];
    float* out = (float*)d_out;

    void *p_xg, *p_hem, *p_xtsbf, *p_catbf, *p_linbf, *p_whhbf, *p_wihbf, *p_hemwbf, *p_logits;
    cudaGetSymbolAddress(&p_xg,     g_xg);
    cudaGetSymbolAddress(&p_hem,    g_hem);
    cudaGetSymbolAddress(&p_xtsbf,  g_xtsbf);
    cudaGetSymbolAddress(&p_catbf,  g_catbf);
    cudaGetSymbolAddress(&p_linbf,  g_linbf);
    cudaGetSymbolAddress(&p_whhbf,  g_whhbf);
    cudaGetSymbolAddress(&p_wihbf,  g_wihbf);
    cudaGetSymbolAddress(&p_hemwbf, g_hemwbf);
    cudaGetSymbolAddress(&p_logits, g_logits);

    cudaFuncSetAttribute(lstm_persist, cudaFuncAttributeMaxDynamicSharedMemorySize, LP_SMEM);

    // 1: gather (bf16 out)
    gather_kernel<<<M5, 128>>>(hidden_en, embed_w, target);

    // 2: fused weight conversions
    conv_all_bf<<<(CV_TOT_Q + 255)/256, 256>>>(W_hh, W_ih, hem_w, lin_w);

    // 3: K1  xg = xts @ W_ih^T + b_ih
    hgemm_nt_bias<<<dim3(G4/128, M5/128), 256>>>(
        (const __nv_bfloat16*)p_xtsbf, HIDI, (const __nv_bfloat16*)p_wihbf, HIDI,
        b_ih, (float*)p_xg, G4, G4, HIDI);

    // 4: persistent LSTM
    lstm_persist<<<LP_NBLK, 256, LP_SMEM>>>(b_hh);

    // 5: K3  hem = h @ hem_w^T + hem_b
    hgemm_nt_bias<<<dim3(H/128, M5/128), 256>>>(
        (const __nv_bfloat16*)p_catbf, KCAT, (const __nv_bfloat16*)p_hemwbf, H,
        hem_b, (float*)p_hem, H, H, H);

    // 6: featatt
    featatt_kernel<<<dim3(16, BATCH), 256>>>(x_em, attw_w, attw_b);

    // 7: attred
    attred_kernel<<<BATCH, 256>>>(att_x_em);

    // 8: K5  logits
    hgemm_nt_bias<<<dim3(NPAD/128, M5/128), 256>>>(
        (const __nv_bfloat16*)p_catbf, KCAT, (const __nv_bfloat16*)p_linbf, KCAT,
        lin_b, (float*)p_logits, NCLS, NCLS, KCAT);

    // 9: K6
    logsoftmax_kernel<<<M5, 256>>>(out);
}